// round 11
// baseline (speedup 1.0000x reference)
#include <cuda_runtime.h>
#include <cuda_bf16.h>
#include <math.h>
#include <stdint.h>

#define T_STEPS 512
#define BATCH   1024
#define HID     64
#define B_TILE  8
#define NT      512

__device__ float g_buf0[BATCH * T_STEPS * HID];   // layer0 -> layer1
__device__ float g_buf1[BATCH * T_STEPS * HID];   // layer1 -> layer2

// ---- smem layout ----
// xh phase buffer: {hi[8][272B], lo[8][272B]} = 4352 B, two phases
#define XH_STRIDE 272
#define PHASE_SZ  4352
#define OFF_GS    8704                    // 16 warps x 160 floats = 10240 B
#define OFF_HEAD  18944                   // 2048 floats (LAST only)
#define SM_TOTAL  27136

__device__ __forceinline__ float sigf(float x) {
    return __fdividef(1.0f, 1.0f + __expf(-x));
}
__device__ __forceinline__ float tanh_fast(float x) {
    float t = fabsf(x);
    float e = __expf(-2.0f * t);
    float r = __fdividef(1.0f - e, 1.0f + e);
    return copysignf(r, x);
}
__device__ __forceinline__ uint32_t packbf(float v0, float v1) {
    __nv_bfloat162 h = __floats2bfloat162_rn(v0, v1);
    return *(uint32_t*)&h;
}
__device__ __forceinline__ void mma16816(float* d, const uint32_t* a, uint32_t b0, uint32_t b1) {
    asm volatile("mma.sync.aligned.m16n8k16.row.col.f32.bf16.bf16.f32 "
                 "{%0,%1,%2,%3}, {%4,%5,%6,%7}, {%8,%9}, {%0,%1,%2,%3};"
                 : "+f"(d[0]), "+f"(d[1]), "+f"(d[2]), "+f"(d[3])
                 : "r"(a[0]), "r"(a[1]), "r"(a[2]), "r"(a[3]), "r"(b0), "r"(b1));
}

// store one xh value as bf16 hi/lo into a phase buffer (base = phase start)
__device__ __forceinline__ void store_bpair(char* base, int b, int k, float v) {
    __nv_bfloat16 hi = __float2bfloat16(v);
    __nv_bfloat16 lo = __float2bfloat16(v - __bfloat162float(hi));
    *(__nv_bfloat16*)(base + b * XH_STRIDE + k * 2)        = hi;
    *(__nv_bfloat16*)(base + 2176 + b * XH_STRIDE + k * 2) = lo;
}

// One CTA = 8 batch elements, 512 threads (16 warps), mma.sync bf16x3.
// K layout PADDED: x part at k in [0,H_K0), h part at k in [H_K0,H_K0+64).
// Persistent dx[3][4] accumulators carry the x-part gates across the barrier:
//   step t:  h-part GEMM (12 MMAs) continues dx -> gates(t); stage; store x(t+1)
//            to next phase; BARRIER; then {epilogue(t) + x-part GEMM for t+1}
//            run in one mixed phase (tensor overlaps MUFU); BARRIER.
template <int IN_W, bool LAST>
__global__ void __launch_bounds__(NT, 1)
lstm_mma(const float* __restrict__ x,     // [B][T][IN_W]
         const float* __restrict__ w_ih,  // [256][IN_W] gate-major rows
         const float* __restrict__ w_hh,  // [256][64]
         const float* __restrict__ b_ih,
         const float* __restrict__ b_hh,
         float* __restrict__ y,           // [B][T][64], or out[B][2] if LAST
         const float* __restrict__ fc1_w, const float* __restrict__ fc1_b,
         const float* __restrict__ fc3_w, const float* __restrict__ fc3_b,
         const float* __restrict__ fc2_w, const float* __restrict__ fc2_b)
{
    constexpr int H_K0  = (IN_W == 6) ? 16 : 64;   // h k-offset (x region padded)
    constexpr int NKC_X = H_K0 / 16;               // x k-chunks (1 or 4)
    constexpr int NKC   = NKC_X + 4;               // total k-chunks (5 or 8)

    extern __shared__ char smem[];
    float* gsp   = (float*)(smem + OFF_GS);
    float* headp = (float*)(smem + OFF_HEAD);

    const int tid = threadIdx.x;
    const int wid = tid >> 5, lid = tid & 31;
    const int b0  = blockIdx.x * B_TILE;

    // ---- fragment identity ----
    const int fg = lid >> 2;
    const int fc = lid & 3;
    const int m0 = 16 * wid + fg;
    const int m1 = m0 + 8;
    const int c4 = 2 * fc;

    // ---- A fragments (weights) -> registers, hi/lo split, once ----
    uint32_t ahi[NKC][4], alo[NKC][4];
    {
        auto wv = [&](int m, int k) -> float {
            int r = (m & 3) * HID + (m >> 2);
            if (k < H_K0) return (k < IN_W) ? w_ih[r * IN_W + k] : 0.0f;
            return w_hh[r * HID + (k - H_K0)];
        };
#pragma unroll
        for (int kc = 0; kc < NKC; kc++) {
            int k0 = 16 * kc + c4;
            float v[8] = { wv(m0, k0),     wv(m0, k0 + 1),
                           wv(m1, k0),     wv(m1, k0 + 1),
                           wv(m0, k0 + 8), wv(m0, k0 + 9),
                           wv(m1, k0 + 8), wv(m1, k0 + 9) };
#pragma unroll
            for (int j = 0; j < 4; j++) {
                float h0f = __bfloat162float(__float2bfloat16(v[2 * j]));
                float h1f = __bfloat162float(__float2bfloat16(v[2 * j + 1]));
                ahi[kc][j] = packbf(v[2 * j], v[2 * j + 1]);
                alo[kc][j] = packbf(v[2 * j] - h0f, v[2 * j + 1] - h1f);
            }
        }
    }

    // ---- epilogue identity (warp-local) + bias ----
    const int ul  = lid >> 3;
    const int u_e = 4 * wid + ul;
    const int b_e = lid & 7;
    float4 bias;
    bias.x = b_ih[0 * HID + u_e] + b_hh[0 * HID + u_e];
    bias.y = b_ih[1 * HID + u_e] + b_hh[1 * HID + u_e];
    bias.z = b_ih[2 * HID + u_e] + b_hh[2 * HID + u_e];
    bias.w = b_ih[3 * HID + u_e] + b_hh[3 * HID + u_e];
    float c_state = 0.0f;
    float* gw = gsp + wid * 160;

    // ---- init: zero both phases; x(0) into phase 0; prologue x-GEMM ----
    for (int i = tid; i < (2 * PHASE_SZ) / 4; i += NT) ((uint32_t*)smem)[i] = 0u;
    __syncthreads();
    if (IN_W == 64) {
        store_bpair(smem, tid >> 6, tid & 63,
                    x[((size_t)(b0 + (tid >> 6)) * T_STEPS + 0) * IN_W + (tid & 63)]);
    } else if (tid < IN_W * B_TILE) {
        int b = tid / IN_W, k = tid - b * IN_W;
        store_bpair(smem, b, k, x[((size_t)(b0 + b) * T_STEPS + 0) * IN_W + k]);
    }
    __syncthreads();

    float dhh[4] = {0.f, 0.f, 0.f, 0.f};
    float dhl[4] = {0.f, 0.f, 0.f, 0.f};
    float dlh[4] = {0.f, 0.f, 0.f, 0.f};
    {   // prologue: x(0) part into dx
        const uint32_t* xh_p = (const uint32_t*)(smem + fg * XH_STRIDE + c4 * 2);
        const uint32_t* xl_p = (const uint32_t*)(smem + 2176 + fg * XH_STRIDE + c4 * 2);
#pragma unroll
        for (int i = 0; i < NKC_X; i++) {
            uint32_t bh0 = xh_p[8 * i], bh1 = xh_p[8 * i + 4];
            uint32_t bl0 = xl_p[8 * i], bl1 = xl_p[8 * i + 4];
            mma16816(dhh, ahi[i], bh0, bh1);
            mma16816(dhl, ahi[i], bl0, bl1);
            mma16816(dlh, alo[i], bh0, bh1);
        }
    }

    for (int t = 0; t < T_STEPS; t++) {
        char* curp = smem + (t & 1) * PHASE_SZ;
        char* nxtp = smem + ((t & 1) ^ 1) * PHASE_SZ;

        // prefetch x(t+1) (global)
        float xpre = 0.f; int pb = 0, pk = 0;
        if (t + 1 < T_STEPS) {
            if (IN_W == 64) {
                pb = tid >> 6; pk = tid & 63;
                xpre = x[((size_t)(b0 + pb) * T_STEPS + (t + 1)) * IN_W + pk];
            } else if (tid < IN_W * B_TILE) {
                pb = tid / IN_W; pk = tid - pb * IN_W;
                xpre = x[((size_t)(b0 + pb) * T_STEPS + (t + 1)) * IN_W + pk];
            }
        }

        // ---- h-part GEMM: continue dx chains (12 MMAs) ----
        {
            const uint32_t* bh_p = (const uint32_t*)(curp + fg * XH_STRIDE + c4 * 2);
            const uint32_t* bl_p = (const uint32_t*)(curp + 2176 + fg * XH_STRIDE + c4 * 2);
#pragma unroll
            for (int i = 0; i < 4; i++) {
                int kc = NKC_X + i;
                uint32_t bh0 = bh_p[8 * kc], bh1 = bh_p[8 * kc + 4];
                uint32_t bl0 = bl_p[8 * kc], bl1 = bl_p[8 * kc + 4];
                mma16816(dhh, ahi[kc], bh0, bh1);
                mma16816(dhl, ahi[kc], bl0, bl1);
                mma16816(dlh, alo[kc], bh0, bh1);
            }
        }
        // ---- stage gates (warp-private, conflict-free) ----
        gw[(c4 + 0) * 20 + fg]     = dhh[0] + (dhl[0] + dlh[0]);
        gw[(c4 + 1) * 20 + fg]     = dhh[1] + (dhl[1] + dlh[1]);
        gw[(c4 + 0) * 20 + 8 + fg] = dhh[2] + (dhl[2] + dlh[2]);
        gw[(c4 + 1) * 20 + 8 + fg] = dhh[3] + (dhl[3] + dlh[3]);
        // ---- store x(t+1) into next phase (x region) ----
        if (t + 1 < T_STEPS) {
            if (IN_W == 64)               store_bpair(nxtp, pb, pk, xpre);
            else if (tid < IN_W * B_TILE) store_bpair(nxtp, pb, pk, xpre);
        }
        __syncthreads();   // BARRIER 1: gates staged + x(t+1) visible

        // ---- mixed phase: epilogue(t)  +  x-part GEMM for t+1 ----
        float4 g = *(const float4*)(gw + b_e * 20 + 4 * ul);

        // reset dx; accumulate x(t+1) part (overlaps the MUFU chain below)
        dhh[0] = dhh[1] = dhh[2] = dhh[3] = 0.f;
        dhl[0] = dhl[1] = dhl[2] = dhl[3] = 0.f;
        dlh[0] = dlh[1] = dlh[2] = dlh[3] = 0.f;
        if (t + 1 < T_STEPS) {
            const uint32_t* xh_p = (const uint32_t*)(nxtp + fg * XH_STRIDE + c4 * 2);
            const uint32_t* xl_p = (const uint32_t*)(nxtp + 2176 + fg * XH_STRIDE + c4 * 2);
#pragma unroll
            for (int i = 0; i < NKC_X; i++) {
                uint32_t bh0 = xh_p[8 * i], bh1 = xh_p[8 * i + 4];
                uint32_t bl0 = xl_p[8 * i], bl1 = xl_p[8 * i + 4];
                mma16816(dhh, ahi[i], bh0, bh1);
                mma16816(dhl, ahi[i], bl0, bl1);
                mma16816(dlh, alo[i], bh0, bh1);
            }
        }

        {   // activations + state update for (u_e, b_e)
            float gi = g.x + bias.x, gf = g.y + bias.y;
            float gg = g.z + bias.z, go = g.w + bias.w;
            float iv = sigf(gi), fv = sigf(gf), gv = tanh_fast(gg), ov = sigf(go);
            c_state = fv * c_state + iv * gv;
            float h = ov * tanh_fast(c_state);

            store_bpair(nxtp, b_e, H_K0 + u_e, h);

            if (!LAST) {
                y[((size_t)(b0 + b_e) * T_STEPS + t) * HID + u_e] = h;
            } else if (t == T_STEPS - 1) {
                headp[b_e * HID + u_e] = h;
            }
        }
        __syncthreads();   // BARRIER 2: h(t) complete in next phase
    }

    // ---- fused MLP head (LAST only) ----
    if (LAST) {
        float* h_s = headp;            // [8][64]
        float* z1  = headp + 512;      // [8][128]
        float* z2  = headp + 1536;     // [8][64]
        __syncthreads();
        for (int v = tid; v < 8 * 128; v += NT) {
            int b = v >> 7, j = v & 127;
            float s = fc1_b[j];
#pragma unroll 8
            for (int k = 0; k < 64; k++) s += h_s[b * 64 + k] * fc1_w[j * 64 + k];
            z1[b * 128 + j] = fmaxf(s, 0.0f);
        }
        __syncthreads();
        for (int v = tid; v < 8 * 64; v += NT) {
            int b = v >> 6, j = v & 63;
            float s = fc3_b[j];
#pragma unroll 8
            for (int k = 0; k < 128; k++) s += z1[b * 128 + k] * fc3_w[j * 128 + k];
            z2[b * 64 + j] = fmaxf(s, 0.0f);
        }
        __syncthreads();
        if (tid < 16) {
            int b = tid >> 1, j = tid & 1;
            float s = fc2_b[j];
#pragma unroll
            for (int k = 0; k < 64; k++) s += z2[b * 64 + k] * fc2_w[j * 64 + k];
            y[(b0 + b) * 2 + j] = s;
        }
    }
}

extern "C" void kernel_launch(void* const* d_in, const int* in_sizes, int n_in,
                              void* d_out, int out_size)
{
    const float* x     = (const float*)d_in[0];
    const float* w_ih0 = (const float*)d_in[1];
    const float* w_hh0 = (const float*)d_in[2];
    const float* b_ih0 = (const float*)d_in[3];
    const float* b_hh0 = (const float*)d_in[4];
    const float* w_ih1 = (const float*)d_in[5];
    const float* w_hh1 = (const float*)d_in[6];
    const float* b_ih1 = (const float*)d_in[7];
    const float* b_hh1 = (const float*)d_in[8];
    const float* w_ih2 = (const float*)d_in[9];
    const float* w_hh2 = (const float*)d_in[10];
    const float* b_ih2 = (const float*)d_in[11];
    const float* b_hh2 = (const float*)d_in[12];
    const float* fc1_w = (const float*)d_in[13];
    const float* fc1_b = (const float*)d_in[14];
    const float* fc3_w = (const float*)d_in[15];
    const float* fc3_b = (const float*)d_in[16];
    const float* fc2_w = (const float*)d_in[17];
    const float* fc2_b = (const float*)d_in[18];
    float* out = (float*)d_out;

    float *buf0 = nullptr, *buf1 = nullptr;
    cudaGetSymbolAddress((void**)&buf0, g_buf0);
    cudaGetSymbolAddress((void**)&buf1, g_buf1);

    const int GRID = BATCH / B_TILE;   // 128

    lstm_mma<6,  false><<<GRID, NT, SM_TOTAL>>>(x,    w_ih0, w_hh0, b_ih0, b_hh0, buf0,
                                                nullptr, nullptr, nullptr, nullptr, nullptr, nullptr);
    lstm_mma<64, false><<<GRID, NT, SM_TOTAL>>>(buf0, w_ih1, w_hh1, b_ih1, b_hh1, buf1,
                                                nullptr, nullptr, nullptr, nullptr, nullptr, nullptr);
    lstm_mma<64, true ><<<GRID, NT, SM_TOTAL>>>(buf1, w_ih2, w_hh2, b_ih2, b_hh2, out,
                                                fc1_w, fc1_b, fc3_w, fc3_b, fc2_w, fc2_b);
}

// round 13
// speedup vs baseline: 1.4313x; 1.4313x over previous
#include <cuda_runtime.h>
#include <cuda_bf16.h>
#include <math.h>
#include <stdint.h>

#define T_STEPS 512
#define BATCH   1024
#define HID     64
#define B_TILE  8
#define NT      512

__device__ float g_buf0[BATCH * T_STEPS * HID];   // layer0 -> layer1
__device__ float g_buf1[BATCH * T_STEPS * HID];   // layer1 -> layer2

// ---- smem byte offsets ----
#define XH_STRIDE 272                     // bytes per batch row (136 bf16)
#define OFF_BHI   0                       // xh hi: 8 rows x 272B = 2176
#define OFF_BLO   2176                    // xh lo: 2176
#define OFF_GS    4352                    // gate staging: 8 batches x 260 floats
#define GS_STRIDE 260
#define OFF_HEAD  12672                   // 2048 floats (LAST only)
#define SM_TOTAL  20864

// tanh.approx.f32: 1 MUFU op (sm_75+), abs err ~1e-4, saturates correctly
__device__ __forceinline__ float tanh_a(float x) {
    float r;
    asm("tanh.approx.f32 %0, %1;" : "=f"(r) : "f"(x));
    return r;
}
__device__ __forceinline__ float sigf(float x) {
    return fmaf(tanh_a(0.5f * x), 0.5f, 0.5f);   // 1 MUFU + 2 FMA
}
__device__ __forceinline__ uint32_t packbf(float v0, float v1) {
    __nv_bfloat162 h = __floats2bfloat162_rn(v0, v1);
    return *(uint32_t*)&h;
}
// D += A(16x16) * B(16x8), bf16 in, f32 accum (sm_80+, valid on base sm_100)
__device__ __forceinline__ void mma16816(float* d, const uint32_t* a, uint32_t b0, uint32_t b1) {
    asm volatile("mma.sync.aligned.m16n8k16.row.col.f32.bf16.bf16.f32 "
                 "{%0,%1,%2,%3}, {%4,%5,%6,%7}, {%8,%9}, {%0,%1,%2,%3};"
                 : "+f"(d[0]), "+f"(d[1]), "+f"(d[2]), "+f"(d[3])
                 : "r"(a[0]), "r"(a[1]), "r"(a[2]), "r"(a[3]), "r"(b0), "r"(b1));
}

// store one xh value as bf16 hi/lo pair
__device__ __forceinline__ void store_bpair(char* smem, int b, int k, float v) {
    __nv_bfloat16 hi = __float2bfloat16(v);
    __nv_bfloat16 lo = __float2bfloat16(v - __bfloat162float(hi));
    *(__nv_bfloat16*)(smem + OFF_BHI + b * XH_STRIDE + k * 2) = hi;
    *(__nv_bfloat16*)(smem + OFF_BLO + b * XH_STRIDE + k * 2) = lo;
}

// One CTA = 8 batch elements, 512 threads (16 warps).  [R9 structure]
// GEMM: gates[256,8] = W[256,K] @ xh[8,K]^T via mma.sync m16n8k16 bf16x3;
//   3 independent accumulator chains (hi*hi, hi*lo, lo*hi) for short dep chains.
//   Warp w owns gate rows 16w..16w+15; A-fragments persistent in registers.
// Staging: gs[batch][row] floats (stride 260), conflict-free STS.32.
// Epilogue: thread = (u = tid&63, b = tid>>6): one LDS.128 -> 4 gates,
//   tanh.approx activations, c/h update, h + x(t+1) back into xh bf16 pairs.
template <int IN_W, bool LAST>
__global__ void __launch_bounds__(NT, 1)
lstm_mma(const float* __restrict__ x,     // [B][T][IN_W]
         const float* __restrict__ w_ih,  // [256][IN_W] gate-major rows
         const float* __restrict__ w_hh,  // [256][64]
         const float* __restrict__ b_ih,
         const float* __restrict__ b_hh,
         float* __restrict__ y,           // [B][T][64], or out[B][2] if LAST
         const float* __restrict__ fc1_w, const float* __restrict__ fc1_b,
         const float* __restrict__ fc3_w, const float* __restrict__ fc3_b,
         const float* __restrict__ fc2_w, const float* __restrict__ fc2_b)
{
    constexpr int K   = IN_W + HID;        // 70 or 128
    constexpr int NKC = (K + 15) / 16;     // k-chunks of 16 (5 or 8)

    extern __shared__ char smem[];
    float* gsp   = (float*)(smem + OFF_GS);
    float* headp = (float*)(smem + OFF_HEAD);

    const int tid = threadIdx.x;
    const int wid = tid >> 5, lid = tid & 31;
    const int b0  = blockIdx.x * B_TILE;

    // ---- fragment identity ----
    const int fg = lid >> 2;
    const int fc = lid & 3;
    const int m0 = 16 * wid + fg;
    const int m1 = m0 + 8;
    const int c4 = 2 * fc;

    // ---- A fragments (weights) -> registers, hi/lo split, once ----
    uint32_t ahi[NKC][4], alo[NKC][4];
    {
        auto wv = [&](int m, int k) -> float {
            int r = (m & 3) * HID + (m >> 2);
            if (k < IN_W) return w_ih[r * IN_W + k];
            if (k < K)    return w_hh[r * HID + (k - IN_W)];
            return 0.0f;
        };
#pragma unroll
        for (int kc = 0; kc < NKC; kc++) {
            int k0 = 16 * kc + c4;
            float v[8] = { wv(m0, k0),     wv(m0, k0 + 1),
                           wv(m1, k0),     wv(m1, k0 + 1),
                           wv(m0, k0 + 8), wv(m0, k0 + 9),
                           wv(m1, k0 + 8), wv(m1, k0 + 9) };
#pragma unroll
            for (int j = 0; j < 4; j++) {
                float h0f = __bfloat162float(__float2bfloat16(v[2 * j]));
                float h1f = __bfloat162float(__float2bfloat16(v[2 * j + 1]));
                ahi[kc][j] = packbf(v[2 * j], v[2 * j + 1]);
                alo[kc][j] = packbf(v[2 * j] - h0f, v[2 * j + 1] - h1f);
            }
        }
    }

    // B-fragment base pointers
    const uint32_t* bhi_p = (const uint32_t*)(smem + OFF_BHI + fg * XH_STRIDE + c4 * 2);
    const uint32_t* blo_p = (const uint32_t*)(smem + OFF_BLO + fg * XH_STRIDE + c4 * 2);

    // ---- epilogue identity + bias ----
    const int u_e = tid & 63, b_e = tid >> 6;
    float4 bias;
    bias.x = b_ih[0 * HID + u_e] + b_hh[0 * HID + u_e];
    bias.y = b_ih[1 * HID + u_e] + b_hh[1 * HID + u_e];
    bias.z = b_ih[2 * HID + u_e] + b_hh[2 * HID + u_e];
    bias.w = b_ih[3 * HID + u_e] + b_hh[3 * HID + u_e];
    float c_state = 0.0f;

    // ---- init: zero xh tiles, then x(0) ----
    for (int i = tid; i < (2 * 2176) / 4; i += NT) ((uint32_t*)smem)[i] = 0u;
    __syncthreads();
    if (IN_W == 64) {
        store_bpair(smem, tid >> 6, tid & 63,
                    x[((size_t)(b0 + (tid >> 6)) * T_STEPS + 0) * IN_W + (tid & 63)]);
    } else if (tid < IN_W * B_TILE) {
        int b = tid / IN_W, k = tid - b * IN_W;
        store_bpair(smem, b, k, x[((size_t)(b0 + b) * T_STEPS + 0) * IN_W + k]);
    }
    __syncthreads();

    for (int t = 0; t < T_STEPS; t++) {
        // prefetch x(t+1)
        float xpre = 0.f; int pb = 0, pk = 0;
        if (t + 1 < T_STEPS) {
            if (IN_W == 64) {
                pb = tid >> 6; pk = tid & 63;
                xpre = x[((size_t)(b0 + pb) * T_STEPS + (t + 1)) * IN_W + pk];
            } else if (tid < IN_W * B_TILE) {
                pb = tid / IN_W; pk = tid - pb * IN_W;
                xpre = x[((size_t)(b0 + pb) * T_STEPS + (t + 1)) * IN_W + pk];
            }
        }

        // ---- GEMM: bf16x3, 3 independent chains ----
        float dhh[4] = {0.f, 0.f, 0.f, 0.f};
        float dhl[4] = {0.f, 0.f, 0.f, 0.f};
        float dlh[4] = {0.f, 0.f, 0.f, 0.f};
#pragma unroll
        for (int kc = 0; kc < NKC; kc++) {
            uint32_t bh0 = bhi_p[8 * kc], bh1 = bhi_p[8 * kc + 4];
            uint32_t bl0 = blo_p[8 * kc], bl1 = blo_p[8 * kc + 4];
            mma16816(dhh, ahi[kc], bh0, bh1);
            mma16816(dhl, ahi[kc], bl0, bl1);
            mma16816(dlh, alo[kc], bh0, bh1);
        }
        // ---- stage: gs[batch][row] (conflict-free STS.32) ----
        gsp[(c4 + 0) * GS_STRIDE + m0] = dhh[0] + (dhl[0] + dlh[0]);
        gsp[(c4 + 1) * GS_STRIDE + m0] = dhh[1] + (dhl[1] + dlh[1]);
        gsp[(c4 + 0) * GS_STRIDE + m1] = dhh[2] + (dhl[2] + dlh[2]);
        gsp[(c4 + 1) * GS_STRIDE + m1] = dhh[3] + (dhl[3] + dlh[3]);
        __syncthreads();   // gates staged; xh reads for step t done

        // ---- epilogue for (u_e, b_e): rows 4u..4u+3 = (i,f,g,o) ----
        {
            float4 g = *(const float4*)(gsp + b_e * GS_STRIDE + 4 * u_e);
            float gi = g.x + bias.x, gf = g.y + bias.y;
            float gg = g.z + bias.z, go = g.w + bias.w;
            float iv = sigf(gi), fv = sigf(gf), gv = tanh_a(gg), ov = sigf(go);
            c_state = fv * c_state + iv * gv;
            float h = ov * tanh_a(c_state);

            store_bpair(smem, b_e, IN_W + u_e, h);

            if (!LAST) {
                y[((size_t)(b0 + b_e) * T_STEPS + t) * HID + u_e] = h;
            } else if (t == T_STEPS - 1) {
                headp[b_e * HID + u_e] = h;
            }
        }
        // x(t+1) into xh
        if (t + 1 < T_STEPS) {
            if (IN_W == 64)                 store_bpair(smem, pb, pk, xpre);
            else if (tid < IN_W * B_TILE)   store_bpair(smem, pb, pk, xpre);
        }
        __syncthreads();   // xh(t+1) ready
    }

    // ---- fused MLP head (LAST only) ----
    if (LAST) {
        float* h_s = headp;            // [8][64]
        float* z1  = headp + 512;      // [8][128]
        float* z2  = headp + 1536;     // [8][64]
        __syncthreads();
        for (int v = tid; v < 8 * 128; v += NT) {
            int b = v >> 7, j = v & 127;
            float s = fc1_b[j];
#pragma unroll 8
            for (int k = 0; k < 64; k++) s += h_s[b * 64 + k] * fc1_w[j * 64 + k];
            z1[b * 128 + j] = fmaxf(s, 0.0f);
        }
        __syncthreads();
        for (int v = tid; v < 8 * 64; v += NT) {
            int b = v >> 6, j = v & 63;
            float s = fc3_b[j];
#pragma unroll 8
            for (int k = 0; k < 128; k++) s += z1[b * 128 + k] * fc3_w[j * 128 + k];
            z2[b * 64 + j] = fmaxf(s, 0.0f);
        }
        __syncthreads();
        if (tid < 16) {
            int b = tid >> 1, j = tid & 1;
            float s = fc2_b[j];
#pragma unroll
            for (int k = 0; k < 64; k++) s += z2[b * 64 + k] * fc2_w[j * 64 + k];
            y[(b0 + b) * 2 + j] = s;
        }
    }
}

extern "C" void kernel_launch(void* const* d_in, const int* in_sizes, int n_in,
                              void* d_out, int out_size)
{
    const float* x     = (const float*)d_in[0];
    const float* w_ih0 = (const float*)d_in[1];
    const float* w_hh0 = (const float*)d_in[2];
    const float* b_ih0 = (const float*)d_in[3];
    const float* b_hh0 = (const float*)d_in[4];
    const float* w_ih1 = (const float*)d_in[5];
    const float* w_hh1 = (const float*)d_in[6];
    const float* b_ih1 = (const float*)d_in[7];
    const float* b_hh1 = (const float*)d_in[8];
    const float* w_ih2 = (const float*)d_in[9];
    const float* w_hh2 = (const float*)d_in[10];
    const float* b_ih2 = (const float*)d_in[11];
    const float* b_hh2 = (const float*)d_in[12];
    const float* fc1_w = (const float*)d_in[13];
    const float* fc1_b = (const float*)d_in[14];
    const float* fc3_w = (const float*)d_in[15];
    const float* fc3_b = (const float*)d_in[16];
    const float* fc2_w = (const float*)d_in[17];
    const float* fc2_b = (const float*)d_in[18];
    float* out = (float*)d_out;

    float *buf0 = nullptr, *buf1 = nullptr;
    cudaGetSymbolAddress((void**)&buf0, g_buf0);
    cudaGetSymbolAddress((void**)&buf1, g_buf1);

    const int GRID = BATCH / B_TILE;   // 128

    lstm_mma<6,  false><<<GRID, NT, SM_TOTAL>>>(x,    w_ih0, w_hh0, b_ih0, b_hh0, buf0,
                                                nullptr, nullptr, nullptr, nullptr, nullptr, nullptr);
    lstm_mma<64, false><<<GRID, NT, SM_TOTAL>>>(buf0, w_ih1, w_hh1, b_ih1, b_hh1, buf1,
                                                nullptr, nullptr, nullptr, nullptr, nullptr, nullptr);
    lstm_mma<64, true ><<<GRID, NT, SM_TOTAL>>>(buf1, w_ih2, w_hh2, b_ih2, b_hh2, out,
                                                fc1_w, fc1_b, fc3_w, fc3_b, fc2_w, fc2_b);
}